// round 6
// baseline (speedup 1.0000x reference)
#include <cuda_runtime.h>
#include <cuda_bf16.h>
#include <math_constants.h>

// x [16384,512] f32, W [512,256] f32, means [1000,256] f32, t scalar (ignored)
// out [16384,1000] f32 one-hot of argmax_j (x@W).means_j
// L2-normalize is a positive per-row scale -> argmax-invariant -> skipped.
// All arithmetic is IEEE fp32 FMA (packed f32x2 = 2 exact lanes) -> rel_err 0.

#define NS   16384
#define DIN  512
#define NF   256
#define NC   1000

__device__ int g_argmax[NS];

// SMEM: featsT[256][128] (131072B) + xs/ms[16][128] (8192B) + ws[16][64] (4096B)
#define SMEM_BYTES (131072 + 8192 + 4096)

// ---- packed f32x2 helpers -------------------------------------------------
__device__ __forceinline__ unsigned long long dup_f32x2(float a) {
    unsigned long long r;
    unsigned int ai = __float_as_uint(a);
    asm("mov.b64 %0, {%1, %1};" : "=l"(r) : "r"(ai));
    return r;
}
__device__ __forceinline__ void ffma2(unsigned long long& d,
                                      unsigned long long a,
                                      unsigned long long b) {
    asm("fma.rn.f32x2 %0, %1, %2, %0;" : "+l"(d) : "l"(a), "l"(b));
}
__device__ __forceinline__ float2 unpk_f32x2(unsigned long long v) {
    unsigned int lo, hi;
    asm("mov.b64 {%0, %1}, %2;" : "=r"(lo), "=r"(hi) : "l"(v));
    float2 f;
    f.x = __uint_as_float(lo);
    f.y = __uint_as_float(hi);
    return f;
}

__global__ void __launch_bounds__(256, 1)
fused_argmax_kernel(const float* __restrict__ x,
                    const float* __restrict__ W,
                    const float* __restrict__ means,
                    int* __restrict__ argout)
{
    extern __shared__ float sm[];
    float* featsT = sm;                   // [256][128]  featsT[feat][row_local]
    float* xs     = sm + 256 * 128;       // [16][128]
    float* ws     = xs + 16 * 128;        // [16][64]
    float* ms     = xs;                   // phase2 reuse: [16][128]

    const int tid = threadIdx.x;
    const int tx  = tid & 15;             // column group
    const int ty  = tid >> 4;             // row group
    const int row0 = blockIdx.x * 128;

    // ---------------- Phase 1: feats(128x256) = x(128x512) @ W(512x256) ----
    // 4 column-chunks of 64; micro-tile 8 rows x 4 cols (packed as 8x2 f32x2).
    for (int ch = 0; ch < 4; ++ch) {
        unsigned long long acc1[8][2];
        #pragma unroll
        for (int r = 0; r < 8; ++r) { acc1[r][0] = 0ull; acc1[r][1] = 0ull; }

        for (int kc = 0; kc < DIN; kc += 16) {
            __syncthreads();
            // x tile transposed: xs[k][row]
            #pragma unroll
            for (int i = 0; i < 2; ++i) {
                int id = tid * 2 + i;           // 0..511
                int r  = id >> 2;               // 0..127
                int q  = id & 3;                // 0..3
                float4 v = *(const float4*)(x + (size_t)(row0 + r) * DIN + kc + q * 4);
                xs[(q * 4 + 0) * 128 + r] = v.x;
                xs[(q * 4 + 1) * 128 + r] = v.y;
                xs[(q * 4 + 2) * 128 + r] = v.z;
                xs[(q * 4 + 3) * 128 + r] = v.w;
            }
            // W tile: ws[k][c]
            {
                int k  = tid >> 4;
                int c4 = tid & 15;
                float4 v = *(const float4*)(W + (size_t)(kc + k) * NF + ch * 64 + c4 * 4);
                *(float4*)(ws + k * 64 + c4 * 4) = v;
            }
            __syncthreads();

            #pragma unroll
            for (int kk = 0; kk < 16; ++kk) {
                float a[8];
                *(float4*)(a)     = *(const float4*)(xs + kk * 128 + ty * 8);
                *(float4*)(a + 4) = *(const float4*)(xs + kk * 128 + ty * 8 + 4);
                unsigned long long a2[8];
                #pragma unroll
                for (int r = 0; r < 8; ++r) a2[r] = dup_f32x2(a[r]);

                ulonglong2 bq = *(const ulonglong2*)(ws + kk * 64 + tx * 4);
                unsigned long long b2[2] = { bq.x, bq.y };

                #pragma unroll
                for (int r = 0; r < 8; ++r) {
                    ffma2(acc1[r][0], a2[r], b2[0]);
                    ffma2(acc1[r][1], a2[r], b2[1]);
                }
            }
        }
        // write chunk into featsT[feat][row]
        #pragma unroll
        for (int cp = 0; cp < 2; ++cp)
            #pragma unroll
            for (int r = 0; r < 8; ++r) {
                float2 v = unpk_f32x2(acc1[r][cp]);
                featsT[(ch * 64 + tx * 4 + cp * 2 + 0) * 128 + (ty * 8 + r)] = v.x;
                featsT[(ch * 64 + tx * 4 + cp * 2 + 1) * 128 + (ty * 8 + r)] = v.y;
            }
    }
    __syncthreads();

    // ---------------- Phase 2: scores = feats @ means^T, fused argmax ------
    float best[8];
    int   bidx[8];
    #pragma unroll
    for (int r = 0; r < 8; ++r) { best[r] = -CUDART_INF_F; bidx[r] = 0; }

    for (int jt = 0; jt < NC; jt += 128) {
        unsigned long long acc[8][4];   // 8 rows x 4 packed pairs = 8x8 scores
        #pragma unroll
        for (int r = 0; r < 8; ++r)
            #pragma unroll
            for (int c = 0; c < 4; ++c) acc[r][c] = 0ull;

        for (int kc = 0; kc < NF; kc += 16) {
            __syncthreads();
            // means tile transposed: ms[k][j]
            #pragma unroll
            for (int i = 0; i < 2; ++i) {
                int id = tid * 2 + i;
                int j  = id >> 2;
                int q  = id & 3;
                int jg = jt + j;
                float4 v = make_float4(0.f, 0.f, 0.f, 0.f);
                if (jg < NC)
                    v = *(const float4*)(means + (size_t)jg * NF + kc + q * 4);
                ms[(q * 4 + 0) * 128 + j] = v.x;
                ms[(q * 4 + 1) * 128 + j] = v.y;
                ms[(q * 4 + 2) * 128 + j] = v.z;
                ms[(q * 4 + 3) * 128 + j] = v.w;
            }
            __syncthreads();

            #pragma unroll
            for (int kk = 0; kk < 16; ++kk) {
                float a[8];
                const float* fr = featsT + (kc + kk) * 128 + ty * 8;
                *(float4*)(a)     = *(const float4*)(fr);
                *(float4*)(a + 4) = *(const float4*)(fr + 4);
                unsigned long long a2[8];
                #pragma unroll
                for (int r = 0; r < 8; ++r) a2[r] = dup_f32x2(a[r]);

                const ulonglong2* mp = (const ulonglong2*)(ms + kk * 128 + tx * 8);
                ulonglong2 b01 = mp[0];
                ulonglong2 b23 = mp[1];
                unsigned long long b2[4] = { b01.x, b01.y, b23.x, b23.y };

                #pragma unroll
                for (int r = 0; r < 8; ++r)
                    #pragma unroll
                    for (int c = 0; c < 4; ++c)
                        ffma2(acc[r][c], a2[r], b2[c]);
            }
        }

        // running argmax (strict >, ascending class index -> earliest-tie kept)
        #pragma unroll
        for (int cp = 0; cp < 4; ++cp) {
            int jg0 = jt + tx * 8 + cp * 2;
            #pragma unroll
            for (int r = 0; r < 8; ++r) {
                float2 v = unpk_f32x2(acc[r][cp]);
                if (jg0 < NC     && v.x > best[r]) { best[r] = v.x; bidx[r] = jg0; }
                if (jg0 + 1 < NC && v.y > best[r]) { best[r] = v.y; bidx[r] = jg0 + 1; }
            }
        }
    }

    // reduce across the 16 tx lanes sharing the same rows (lane = (ty&1)*16+tx)
    #pragma unroll
    for (int r = 0; r < 8; ++r) {
        float v  = best[r];
        int   id = bidx[r];
        #pragma unroll
        for (int off = 8; off >= 1; off >>= 1) {
            float ov = __shfl_xor_sync(0xffffffffu, v, off);
            int   oi = __shfl_xor_sync(0xffffffffu, id, off);
            if (ov > v || (ov == v && oi < id)) { v = ov; id = oi; }
        }
        if (tx == 0)
            argout[row0 + ty * 8 + r] = id;
    }
}

// One-hot writer: 1000 % 4 == 0 -> float4 never crosses a row boundary.
__global__ void onehot_kernel(const int* __restrict__ argmax, float* __restrict__ out)
{
    int t = blockIdx.x * blockDim.x + threadIdx.x;
    int f = t * 4;
    int row = f / NC;
    int col = f - row * NC;
    int idx = __ldg(argmax + row);
    float4 v;
    v.x = (col + 0 == idx) ? 1.0f : 0.0f;
    v.y = (col + 1 == idx) ? 1.0f : 0.0f;
    v.z = (col + 2 == idx) ? 1.0f : 0.0f;
    v.w = (col + 3 == idx) ? 1.0f : 0.0f;
    *(float4*)(out + f) = v;
}

extern "C" void kernel_launch(void* const* d_in, const int* in_sizes, int n_in,
                              void* d_out, int out_size)
{
    const float* x     = (const float*)d_in[0];
    const float* W     = (const float*)d_in[1];
    const float* means = (const float*)d_in[2];
    float* out = (float*)d_out;

    int* argout;
    cudaGetSymbolAddress((void**)&argout, g_argmax);

    static bool attr_set = false;
    if (!attr_set) {
        cudaFuncSetAttribute(fused_argmax_kernel,
                             cudaFuncAttributeMaxDynamicSharedMemorySize, SMEM_BYTES);
        attr_set = true;
    }

    fused_argmax_kernel<<<NS / 128, 256, SMEM_BYTES>>>(x, W, means, argout);

    int total4 = NS * NC / 4;
    onehot_kernel<<<total4 / 256, 256>>>(argout, out);
}